// round 6
// baseline (speedup 1.0000x reference)
#include <cuda_runtime.h>
#include <cstdint>

// Problem shape (fixed by the dataset): B=8, N=M=2048, 3-D points.
#define kB 8
#define kN 2048
#define kM 2048

// Pass A/C geometry: 256 threads = 8 warps, 4 rows per warp -> 32 rows/CTA
#define ROWS_PER_WARP 4
#define WARPS_AC 8
#define ROWS_PER_CTA (ROWS_PER_WARP * WARPS_AC)     // 32
#define GRID_AC (kB * (kN / ROWS_PER_CTA))          // 512

// Pass B geometry: thread-per-column tile of 256, n split into chunks of 256
#define MTILE 256
#define NCHUNK 256
#define NCHUNKS (kN / NCHUNK)                       // 8
#define GRID_B (kB * (kM / MTILE) * NCHUNKS)        // 512

#define SKIP_X (-60.0f)       // in log2 units: 2^-60 per-element bound
#define LOG2E 1.4426950408889634f

// ---------------- scratch (static __device__, no allocation) ----------------
__device__ float4 g_P1[kB][kN];                 // (x,y,z, unused)
__device__ float4 g_P2[kB][kM];
__device__ float  g_rowmin[kB][kN];             // min_m d2
__device__ float  g_rowscale[kB][kN];
__device__ float  g_remainL[kB][kN];
__device__ float  g_remainR[kB][kM];
__device__ float  g_remReff[kB][kM];            // remainR_old * cscale
__device__ float  g_colsum[kB][NCHUNKS][kM];
__device__ float  g_colsumd[kB][NCHUNKS][kM];

// ---------------- helpers ----------------
__device__ __forceinline__ float ex2f(float x) {
    float r; asm("ex2.approx.f32 %0, %1;" : "=f"(r) : "f"(x)); return r;
}
__device__ __forceinline__ float sqrt_apx(float x) {
    float r; asm("sqrt.approx.f32 %0, %1;" : "=f"(r) : "f"(x)); return r;
}
__device__ __forceinline__ float warp_sum(float v) {
    #pragma unroll
    for (int o = 16; o; o >>= 1) v += __shfl_xor_sync(0xffffffffu, v, o);
    return v;
}
__device__ __forceinline__ float warp_min(float v) {
    #pragma unroll
    for (int o = 16; o; o >>= 1) v = fminf(v, __shfl_xor_sync(0xffffffffu, v, o));
    return v;
}

// ---------------- init: pack points, init remain masses, zero output ----------------
__global__ void k_init(const float* __restrict__ in1, const float* __restrict__ in2,
                       float* __restrict__ out) {
    int idx = blockIdx.x * blockDim.x + threadIdx.x;   // over kB*kN
    if (idx < kB * kN) {
        int b = idx / kN, n = idx % kN;
        const float* p1 = in1 + (size_t)idx * 3;
        const float* p2 = in2 + (size_t)idx * 3;
        g_P1[b][n] = make_float4(p1[0], p1[1], p1[2], 0.f);
        g_P2[b][n] = make_float4(p2[0], p2[1], p2[2], 0.f);
        g_remainL[b][n] = 1.0f;   // multiL = 1 (N == M)
        g_remainR[b][n] = 1.0f;   // multiR = 1
    }
    if (idx < kB) out[idx] = 0.0f;
}

// ---------------- rowmin: min_m d2 per left point ----------------
__global__ void __launch_bounds__(256) k_rowmin() {
    __shared__ float4 s2[kM];
    int cta = blockIdx.x;
    int b = cta / (kN / ROWS_PER_CTA);
    int rowbase = (cta % (kN / ROWS_PER_CTA)) * ROWS_PER_CTA;
    for (int i = threadIdx.x; i < kM; i += blockDim.x) s2[i] = g_P2[b][i];
    __syncthreads();
    int warp = threadIdx.x >> 5, lane = threadIdx.x & 31;
    float x1[ROWS_PER_WARP], y1[ROWS_PER_WARP], z1[ROWS_PER_WARP], mn[ROWS_PER_WARP];
    #pragma unroll
    for (int r = 0; r < ROWS_PER_WARP; r++) {
        int n = rowbase + warp * ROWS_PER_WARP + r;
        float4 p = g_P1[b][n];
        x1[r] = p.x; y1[r] = p.y; z1[r] = p.z; mn[r] = 3.4e38f;
    }
    for (int m = lane; m < kM; m += 32) {
        float4 q = s2[m];
        #pragma unroll
        for (int r = 0; r < ROWS_PER_WARP; r++) {
            float dx = x1[r] - q.x, dy = y1[r] - q.y, dz = z1[r] - q.z;
            float d2 = dx * dx + dy * dy + dz * dz;
            mn[r] = fminf(mn[r], d2);
        }
    }
    #pragma unroll
    for (int r = 0; r < ROWS_PER_WARP; r++) {
        float v = warp_min(mn[r]);
        if (lane == 0) g_rowmin[b][rowbase + warp * ROWS_PER_WARP + r] = v;
    }
}

// ---------------- pass A: row sums -> rowscale ----------------
__global__ void __launch_bounds__(256) k_passA(float lvl2) {
    __shared__ float4 s2[kM];     // (x,y,z, remainR)
    int cta = blockIdx.x;
    int b = cta / (kN / ROWS_PER_CTA);
    int rowbase = (cta % (kN / ROWS_PER_CTA)) * ROWS_PER_CTA;
    for (int i = threadIdx.x; i < kM; i += blockDim.x) {
        float4 p = g_P2[b][i]; p.w = g_remainR[b][i]; s2[i] = p;
    }
    __syncthreads();
    int warp = threadIdx.x >> 5, lane = threadIdx.x & 31;
    float x1[ROWS_PER_WARP], y1[ROWS_PER_WARP], z1[ROWS_PER_WARP], acc[ROWS_PER_WARP];
    bool live[ROWS_PER_WARP]; bool any = false;
    #pragma unroll
    for (int r = 0; r < ROWS_PER_WARP; r++) {
        int n = rowbase + warp * ROWS_PER_WARP + r;
        float4 p = g_P1[b][n];
        x1[r] = p.x; y1[r] = p.y; z1[r] = p.z; acc[r] = 0.f;
        live[r] = (lvl2 * g_rowmin[b][n] >= SKIP_X) && (g_remainL[b][n] > 0.f);
        any |= live[r];
    }
    if (any) {
        for (int m = lane; m < kM; m += 32) {
            float4 q = s2[m];
            #pragma unroll
            for (int r = 0; r < ROWS_PER_WARP; r++) {
                float dx = x1[r] - q.x, dy = y1[r] - q.y, dz = z1[r] - q.z;
                float d2 = dx * dx + dy * dy + dz * dz;
                float e = ex2f(lvl2 * d2);
                acc[r] = fmaf(e, q.w, acc[r]);
            }
        }
    }
    #pragma unroll
    for (int r = 0; r < ROWS_PER_WARP; r++) {
        float s = warp_sum(acc[r]);
        if (lane == 0) {
            int n = rowbase + warp * ROWS_PER_WARP + r;
            float rs = live[r] ? (g_remainL[b][n] / (s + 1e-9f)) : 0.0f;
            g_rowscale[b][n] = rs;
        }
    }
}

// ---------------- pass B: partial column sums (and distance-weighted) ----------------
__global__ void __launch_bounds__(256) k_passB(float lvl2) {
    __shared__ float4 s1[NCHUNK];  // (x,y,z, rowscale)
    int cta = blockIdx.x;
    int b = cta / ((kM / MTILE) * NCHUNKS);
    int rem = cta % ((kM / MTILE) * NCHUNKS);
    int mtile = rem / NCHUNKS;
    int chunk = rem % NCHUNKS;
    int nbase = chunk * NCHUNK;
    for (int i = threadIdx.x; i < NCHUNK; i += blockDim.x) {
        float4 p = g_P1[b][nbase + i]; p.w = g_rowscale[b][nbase + i]; s1[i] = p;
    }
    __syncthreads();
    int m = mtile * MTILE + threadIdx.x;
    float4 q = g_P2[b][m];
    float remR = g_remainR[b][m];
    float cs = 0.f, csd = 0.f;
    #pragma unroll 4
    for (int i = 0; i < NCHUNK; i++) {
        float4 p = s1[i];
        if (p.w == 0.f) continue;           // warp-uniform (same i for all lanes)
        float dx = p.x - q.x, dy = p.y - q.y, dz = p.z - q.z;
        float d2 = dx * dx + dy * dy + dz * dz;
        float e = ex2f(lvl2 * d2);
        float w = e * (p.w * remR);
        cs += w;
        csd = fmaf(w, sqrt_apx(d2), csd);
    }
    g_colsum[b][chunk][m] = cs;
    g_colsumd[b][chunk][m] = csd;
}

// ---------------- pass E: clip columns, cost, remainR update ----------------
__global__ void __launch_bounds__(256) k_passE(float* __restrict__ out) {
    __shared__ float red[256];
    int b = blockIdx.x;
    float cpart = 0.f;
    for (int m = threadIdx.x; m < kM; m += 256) {
        float cs = 0.f, csd = 0.f;
        #pragma unroll
        for (int c = 0; c < NCHUNKS; c++) { cs += g_colsum[b][c][m]; csd += g_colsumd[b][c][m]; }
        float rr = g_remainR[b][m];
        float csc = fminf(rr / (cs + 1e-9f), 1.0f);
        cpart += csd * csc;
        g_remReff[b][m] = rr * csc;
        g_remainR[b][m] = fmaxf(rr - cs * csc, 0.0f);
    }
    red[threadIdx.x] = cpart;
    __syncthreads();
    #pragma unroll
    for (int s = 128; s > 0; s >>= 1) {
        if (threadIdx.x < s) red[threadIdx.x] += red[threadIdx.x + s];
        __syncthreads();
    }
    if (threadIdx.x == 0) out[b] += red[0];
}

// ---------------- pass C: remainL update ----------------
__global__ void __launch_bounds__(256) k_passC(float lvl2) {
    __shared__ float4 s2[kM];      // (x,y,z, remReff)
    int cta = blockIdx.x;
    int b = cta / (kN / ROWS_PER_CTA);
    int rowbase = (cta % (kN / ROWS_PER_CTA)) * ROWS_PER_CTA;
    for (int i = threadIdx.x; i < kM; i += blockDim.x) {
        float4 p = g_P2[b][i]; p.w = g_remReff[b][i]; s2[i] = p;
    }
    __syncthreads();
    int warp = threadIdx.x >> 5, lane = threadIdx.x & 31;
    float x1[ROWS_PER_WARP], y1[ROWS_PER_WARP], z1[ROWS_PER_WARP], acc[ROWS_PER_WARP], rsc[ROWS_PER_WARP];
    bool any = false;
    #pragma unroll
    for (int r = 0; r < ROWS_PER_WARP; r++) {
        int n = rowbase + warp * ROWS_PER_WARP + r;
        float4 p = g_P1[b][n];
        x1[r] = p.x; y1[r] = p.y; z1[r] = p.z; acc[r] = 0.f;
        rsc[r] = g_rowscale[b][n];
        any |= (rsc[r] != 0.f);
    }
    if (any) {
        for (int m = lane; m < kM; m += 32) {
            float4 q = s2[m];
            #pragma unroll
            for (int r = 0; r < ROWS_PER_WARP; r++) {
                float dx = x1[r] - q.x, dy = y1[r] - q.y, dz = z1[r] - q.z;
                float d2 = dx * dx + dy * dy + dz * dz;
                float e = ex2f(lvl2 * d2);
                acc[r] = fmaf(e, q.w, acc[r]);
            }
        }
    }
    #pragma unroll
    for (int r = 0; r < ROWS_PER_WARP; r++) {
        float s = warp_sum(acc[r]);
        if (lane == 0 && rsc[r] != 0.f) {
            int n = rowbase + warp * ROWS_PER_WARP + r;
            g_remainL[b][n] = fmaxf(g_remainL[b][n] - rsc[r] * s, 0.0f);
        }
    }
}

// ---------------- launch ----------------
extern "C" void kernel_launch(void* const* d_in, const int* in_sizes, int n_in,
                              void* d_out, int out_size) {
    const float* in1 = (const float*)d_in[0];
    const float* in2 = (const float*)d_in[1];
    float* out = (float*)d_out;

    static const float levels[10] = {
        -16384.f, -4096.f, -1024.f, -256.f, -64.f, -16.f, -4.f, -1.f, -0.25f, 0.f
    };

    k_init<<<(kB * kN + 255) / 256, 256>>>(in1, in2, out);
    k_rowmin<<<GRID_AC, 256>>>();
    for (int j = 0; j < 10; j++) {
        float lvl2 = levels[j] * LOG2E;   // exp(l*d2) = 2^(lvl2*d2)
        k_passA<<<GRID_AC, 256>>>(lvl2);
        k_passB<<<GRID_B, 256>>>(lvl2);
        k_passE<<<kB, 256>>>(out);
        k_passC<<<GRID_AC, 256>>>(lvl2);
    }
}

// round 7
// speedup vs baseline: 2.0814x; 2.0814x over previous
#include <cuda_runtime.h>

// Problem shape (fixed by the dataset): B=8, N=M=2048, 3-D points.
#define kB 8
#define kN 2048
#define kM 2048

// Fused A+C geometry: 256 threads = 8 warps, 4 rows/warp -> 32 rows/CTA
#define RPW 4
#define WARPS_AC 8
#define ROWS_PER_CTA (RPW * WARPS_AC)               // 32
#define GRID_AC (kB * (kN / ROWS_PER_CTA))          // 512

// Pass B geometry: thread-per-column tile of 256, n split into chunks of 256
#define MTILE 256
#define NCHUNK 256
#define NCHUNKS (kN / NCHUNK)                       // 8
#define GRID_B (kB * (kM / MTILE) * NCHUNKS)        // 512

#define SKIP_X (-60.0f)       // log2-units skip threshold
#define LOG2E 1.4426950408889634f

// ---------------- scratch (static __device__, no allocation) ----------------
__device__ float4 g_P1[kB][kN];                 // (x,y,z,|p|^2)
__device__ float4 g_P2[kB][kM];                 // (x,y,z,|q|^2)
__device__ float  g_rowmin[kB][kN];             // min_m d2
__device__ float  g_rowscale[kB][kN];
__device__ float  g_remainL[kB][kN];
__device__ float  g_remainR[kB][kM];
__device__ float  g_remReff[kB][kM];            // remainR_old * cscale
__device__ float  g_colsum[kB][NCHUNKS][kM];
__device__ float  g_colsumd[kB][NCHUNKS][kM];
__device__ float  g_sumRemR[kB];

// ---------------- helpers ----------------
__device__ __forceinline__ float ex2f(float x) {
    float r; asm("ex2.approx.f32 %0, %1;" : "=f"(r) : "f"(x)); return r;
}
__device__ __forceinline__ float sqrt_apx(float x) {
    float r; asm("sqrt.approx.f32 %0, %1;" : "=f"(r) : "f"(x)); return r;
}
__device__ __forceinline__ float warp_sum(float v) {
    #pragma unroll
    for (int o = 16; o; o >>= 1) v += __shfl_xor_sync(0xffffffffu, v, o);
    return v;
}
__device__ __forceinline__ float warp_min(float v) {
    #pragma unroll
    for (int o = 16; o; o >>= 1) v = fminf(v, __shfl_xor_sync(0xffffffffu, v, o));
    return v;
}

// ---------------- init ----------------
__global__ void k_init(const float* __restrict__ in1, const float* __restrict__ in2,
                       float* __restrict__ out) {
    int idx = blockIdx.x * blockDim.x + threadIdx.x;   // over kB*kN
    if (idx < kB * kN) {
        int b = idx / kN, n = idx % kN;
        const float* p1 = in1 + (size_t)idx * 3;
        const float* p2 = in2 + (size_t)idx * 3;
        float x1 = p1[0], y1 = p1[1], z1 = p1[2];
        float x2 = p2[0], y2 = p2[1], z2 = p2[2];
        g_P1[b][n] = make_float4(x1, y1, z1, x1 * x1 + y1 * y1 + z1 * z1);
        g_P2[b][n] = make_float4(x2, y2, z2, x2 * x2 + y2 * y2 + z2 * z2);
        g_remainL[b][n] = 1.0f;   // multiL = 1 (N == M)
        g_remainR[b][n] = 1.0f;   // multiR = 1
        g_rowscale[b][n] = 0.0f;  // "previous level" state for fused A+C
        g_remReff[b][n] = 0.0f;
    }
    if (idx < kB) { out[idx] = 0.0f; g_sumRemR[idx] = 0.0f; }
}

// ---------------- rowmin: min_m d2 per left point (one-time) ----------------
__global__ void __launch_bounds__(256) k_rowmin() {
    __shared__ float4 s2[kM];
    int cta = blockIdx.x;
    int b = cta / (kN / ROWS_PER_CTA);
    int rowbase = (cta % (kN / ROWS_PER_CTA)) * ROWS_PER_CTA;
    for (int i = threadIdx.x; i < kM; i += blockDim.x) s2[i] = g_P2[b][i];
    __syncthreads();
    int warp = threadIdx.x >> 5, lane = threadIdx.x & 31;
    float x1[RPW], y1[RPW], z1[RPW], mn[RPW];
    #pragma unroll
    for (int r = 0; r < RPW; r++) {
        int n = rowbase + warp * RPW + r;
        float4 p = g_P1[b][n];
        x1[r] = p.x; y1[r] = p.y; z1[r] = p.z; mn[r] = 3.4e38f;
    }
    for (int m = lane; m < kM; m += 32) {
        float4 q = s2[m];
        #pragma unroll
        for (int r = 0; r < RPW; r++) {
            float dx = x1[r] - q.x, dy = y1[r] - q.y, dz = z1[r] - q.z;
            float d2 = dx * dx + dy * dy + dz * dz;
            mn[r] = fminf(mn[r], d2);
        }
    }
    #pragma unroll
    for (int r = 0; r < RPW; r++) {
        float v = warp_min(mn[r]);
        if (lane == 0) g_rowmin[b][rowbase + warp * RPW + r] = v;
    }
}

// ---------------- fused pass: C(level j-1) + A(level j) ----------------
// accC[r] = sum_m exp(lvl_p*d2)*remReff[m]   (drives remainL update)
// accA[r] = sum_m exp(lvl_c*d2)*remainR[m]   (drives rowscale)
template<bool DOA, bool DOC>
__device__ __forceinline__ void ac_inner(
    const float4* __restrict__ s2, const float2* __restrict__ sw,
    int lane, float lvl2p, float lvl2c,
    const float (&bx)[RPW], const float (&by)[RPW], const float (&bz)[RPW],
    const float (&bc)[RPW], float (&accA)[RPW], float (&accC)[RPW])
{
    #pragma unroll 4
    for (int m = lane; m < kM; m += 32) {
        float4 q = s2[m];
        float2 w = sw[m];                      // x = remReff(prev), y = remainR(new)
        #pragma unroll
        for (int r = 0; r < RPW; r++) {
            float d2 = q.w + bc[r];
            d2 = fmaf(bx[r], q.x, d2);
            d2 = fmaf(by[r], q.y, d2);
            d2 = fmaf(bz[r], q.z, d2);         // |p|^2+|q|^2-2p.q
            if (DOC) { float e = ex2f(lvl2p * d2); accC[r] = fmaf(e, w.x, accC[r]); }
            if (DOA) { float e = ex2f(lvl2c * d2); accA[r] = fmaf(e, w.y, accA[r]); }
        }
    }
}

__global__ void __launch_bounds__(256) k_fusedAC(float lvl2p, float lvl2c, int aTrivial) {
    __shared__ float4 s2[kM];                  // 32 KB: (x,y,z,|q|^2)
    __shared__ float2 sw[kM];                  // 16 KB: (remReff, remainR)
    int cta = blockIdx.x;
    int b = cta / (kN / ROWS_PER_CTA);
    int rowbase = (cta % (kN / ROWS_PER_CTA)) * ROWS_PER_CTA;
    int warp = threadIdx.x >> 5, lane = threadIdx.x & 31;

    float bx[RPW], by[RPW], bz[RPW], bc[RPW], rsPrev[RPW];
    bool liveA[RPW];
    bool anyA = false, anyC = false;
    #pragma unroll
    for (int r = 0; r < RPW; r++) {
        int n = rowbase + warp * RPW + r;
        float4 p = g_P1[b][n];
        bx[r] = -2.0f * p.x; by[r] = -2.0f * p.y; bz[r] = -2.0f * p.z; bc[r] = p.w;
        rsPrev[r] = g_rowscale[b][n];
        float rm = g_rowmin[b][n];
        liveA[r] = (!aTrivial) && (lvl2c * rm >= SKIP_X);
        anyA |= liveA[r];
        anyC |= (rsPrev[r] != 0.0f);
    }

    // CTA-level dead check BEFORE paying for the 48KB smem fill
    int ctaAny = __syncthreads_or((anyA || anyC) ? 1 : 0);

    float accA[RPW], accC[RPW];
    #pragma unroll
    for (int r = 0; r < RPW; r++) { accA[r] = 0.0f; accC[r] = 0.0f; }

    if (ctaAny) {
        for (int i = threadIdx.x; i < kM; i += 256) {
            s2[i] = g_P2[b][i];
            sw[i] = make_float2(g_remReff[b][i], g_remainR[b][i]);
        }
        __syncthreads();
        if (anyA & anyC)      ac_inner<true,  true >(s2, sw, lane, lvl2p, lvl2c, bx, by, bz, bc, accA, accC);
        else if (anyC)        ac_inner<false, true >(s2, sw, lane, lvl2p, lvl2c, bx, by, bz, bc, accA, accC);
        else if (anyA)        ac_inner<true,  false>(s2, sw, lane, lvl2p, lvl2c, bx, by, bz, bc, accA, accC);
    }

    #pragma unroll
    for (int r = 0; r < RPW; r++) {
        float sC = warp_sum(accC[r]);
        float sA = warp_sum(accA[r]);
        if (lane == 0) {
            int n = rowbase + warp * RPW + r;
            float remL = g_remainL[b][n];
            remL = fmaxf(remL - rsPrev[r] * sC, 0.0f);   // C(j-1): remainL update
            g_remainL[b][n] = remL;
            float rowsum = aTrivial ? g_sumRemR[b] : sA; // level 0: exp==1 -> sum(remainR)
            float rs = (aTrivial || liveA[r]) ? (remL / (rowsum + 1e-9f)) : 0.0f;
            g_rowscale[b][n] = rs;                       // A(j): rowscale
        }
    }
}

// ---------------- pass B: partial column sums (+ distance-weighted) ----------------
__global__ void __launch_bounds__(256) k_passB(float lvl2) {
    __shared__ float4 s1[NCHUNK];
    __shared__ float  s1w[NCHUNK];
    int cta = blockIdx.x;
    int b = cta / ((kM / MTILE) * NCHUNKS);
    int rem = cta % ((kM / MTILE) * NCHUNKS);
    int mtile = rem / NCHUNKS;
    int chunk = rem % NCHUNKS;
    int nbase = chunk * NCHUNK;

    int i = threadIdx.x;                        // NCHUNK == blockDim
    float rs = g_rowscale[b][nbase + i];
    s1[i] = g_P1[b][nbase + i];
    s1w[i] = rs;
    int anyLive = __syncthreads_or(rs != 0.0f ? 1 : 0);

    int m = mtile * MTILE + threadIdx.x;
    if (!anyLive) {                             // whole chunk dead: write zeros, exit
        g_colsum[b][chunk][m] = 0.0f;
        g_colsumd[b][chunk][m] = 0.0f;
        return;
    }
    float4 q = g_P2[b][m];
    float qx = -2.0f * q.x, qy = -2.0f * q.y, qz = -2.0f * q.z, cq = q.w;
    float cs = 0.0f, csd = 0.0f;
    #pragma unroll 8
    for (int ii = 0; ii < NCHUNK; ii++) {
        float4 p = s1[ii];
        float w = s1w[ii];
        float d2 = p.w + cq;
        d2 = fmaf(qx, p.x, d2);
        d2 = fmaf(qy, p.y, d2);
        d2 = fmaf(qz, p.z, d2);
        d2 = fmaxf(d2, 0.0f);                   // guard sqrt vs rounding
        float e = ex2f(lvl2 * d2);
        float t = e * w;                        // w==0 rows contribute exact 0
        cs += t;
        csd = fmaf(t, sqrt_apx(d2), csd);
    }
    float remR = g_remainR[b][m];               // hoisted out of the reduction
    g_colsum[b][chunk][m]  = cs * remR;
    g_colsumd[b][chunk][m] = csd * remR;
}

// ---------------- pass E: clip columns, cost, remainR update, sum(remainR) ----------------
__global__ void __launch_bounds__(256) k_passE(float* __restrict__ out) {
    __shared__ float red[256], red2[256];
    int b = blockIdx.x;
    float cpart = 0.0f, rpart = 0.0f;
    for (int m = threadIdx.x; m < kM; m += 256) {
        float cs = 0.0f, csd = 0.0f;
        #pragma unroll
        for (int c = 0; c < NCHUNKS; c++) { cs += g_colsum[b][c][m]; csd += g_colsumd[b][c][m]; }
        float rr = g_remainR[b][m];
        float csc = fminf(rr / (cs + 1e-9f), 1.0f);
        cpart += csd * csc;
        g_remReff[b][m] = rr * csc;
        float nr = fmaxf(rr - cs * csc, 0.0f);
        g_remainR[b][m] = nr;
        rpart += nr;
    }
    red[threadIdx.x] = cpart;
    red2[threadIdx.x] = rpart;
    __syncthreads();
    #pragma unroll
    for (int s = 128; s > 0; s >>= 1) {
        if (threadIdx.x < s) { red[threadIdx.x] += red[threadIdx.x + s];
                               red2[threadIdx.x] += red2[threadIdx.x + s]; }
        __syncthreads();
    }
    if (threadIdx.x == 0) { out[b] += red[0]; g_sumRemR[b] = red2[0]; }
}

// ---------------- launch ----------------
extern "C" void kernel_launch(void* const* d_in, const int* in_sizes, int n_in,
                              void* d_out, int out_size) {
    const float* in1 = (const float*)d_in[0];
    const float* in2 = (const float*)d_in[1];
    float* out = (float*)d_out;

    static const float levels[10] = {
        -16384.f, -4096.f, -1024.f, -256.f, -64.f, -16.f, -4.f, -1.f, -0.25f, 0.f
    };

    k_init<<<(kB * kN + 255) / 256, 256>>>(in1, in2, out);
    k_rowmin<<<GRID_AC, 256>>>();
    float prev = 0.0f;                           // j=0: rowscale==0 everywhere -> C part inert
    for (int j = 0; j < 10; j++) {
        float lc = levels[j] * LOG2E;            // exp(l*d2) = 2^(lc*d2)
        k_fusedAC<<<GRID_AC, 256>>>(prev, lc, (j == 9) ? 1 : 0);
        k_passB<<<GRID_B, 256>>>(lc);
        k_passE<<<kB, 256>>>(out);
        prev = lc;
    }
}

// round 8
// speedup vs baseline: 2.4595x; 1.1817x over previous
#include <cuda_runtime.h>
#include <cuda_fp16.h>

// Problem shape (fixed by the dataset): B=8, N=M=2048, 3-D points.
#define kB 8
#define kN 2048
#define kM 2048

// Fused A+C geometry: 256 threads = 8 warps, 4 rows/warp -> 32 rows/CTA
#define RPW 4
#define ROWS_PER_CTA 32
#define GRID_AC (kB * kN / ROWS_PER_CTA)            // 512

// Pass B / dprep geometry: thread-per-column tile of 256, n chunks of 256
#define MTILE 256
#define NCHUNK 256
#define NCHUNKS (kN / NCHUNK)                       // 8
#define GRID_B (kB * (kM / MTILE) * NCHUNKS)        // 512

#define SKIP_X (-60.0f)
#define LOG2E 1.4426950408889634f
#define DEAD_LG (-1e30f)     // stands in for log2(0); ex2 underflows to exact 0

typedef unsigned long long ull;

// ---------------- scratch (static __device__, no allocation) ----------------
__device__ float4  g_P1[kB][kN];                // (x,y,z,|p|^2)
__device__ float4  g_P2[kB][kM];                // (x,y,z,|q|^2)
__device__ float   g_rowmin[kB][kN];
__device__ float   g_rowscale[kB][kN];
__device__ float4  g_rowB[kB][kN];              // (l2*-2x, l2*-2y, l2*-2z, l2*|p|^2 + lg2(rs))
__device__ float   g_remainL[kB][kN];
__device__ float   g_remainR[kB][kM];
__device__ float   g_remReff[kB][kM];
__device__ float   g_colsum[kB][NCHUNKS][kM];
__device__ float   g_colsumd[kB][NCHUNKS][kM];
__device__ float   g_costPart[kB][kM / MTILE];
__device__ float   g_sumRPart[kB][kM / MTILE];
__device__ __half2 g_d16[kB][kN / 2][kM];       // 64 MB distance table, pair over n

// ---------------- helpers ----------------
__device__ __forceinline__ float ex2f(float x) {
    float r; asm("ex2.approx.f32 %0, %1;" : "=f"(r) : "f"(x)); return r;
}
__device__ __forceinline__ float lg2f(float x) {
    float r; asm("lg2.approx.f32 %0, %1;" : "=f"(r) : "f"(x)); return r;
}
__device__ __forceinline__ float sqrt_apx(float x) {
    float r; asm("sqrt.approx.f32 %0, %1;" : "=f"(r) : "f"(x)); return r;
}
__device__ __forceinline__ ull pk(float lo, float hi) {
    ull r; asm("mov.b64 %0, {%1, %2};" : "=l"(r) : "f"(lo), "f"(hi)); return r;
}
__device__ __forceinline__ float2 upk(ull v) {
    float lo, hi; asm("mov.b64 {%0, %1}, %2;" : "=f"(lo), "=f"(hi) : "l"(v));
    return make_float2(lo, hi);
}
__device__ __forceinline__ ull fma2(ull a, ull b, ull c) {
    ull r; asm("fma.rn.f32x2 %0, %1, %2, %3;" : "=l"(r) : "l"(a), "l"(b), "l"(c)); return r;
}
__device__ __forceinline__ ull add2(ull a, ull b) {
    ull r; asm("add.rn.f32x2 %0, %1, %2;" : "=l"(r) : "l"(a), "l"(b)); return r;
}
__device__ __forceinline__ ull mul2(ull a, ull b) {
    ull r; asm("mul.rn.f32x2 %0, %1, %2;" : "=l"(r) : "l"(a), "l"(b)); return r;
}
__device__ __forceinline__ float warp_sum(float v) {
    #pragma unroll
    for (int o = 16; o; o >>= 1) v += __shfl_xor_sync(0xffffffffu, v, o);
    return v;
}
__device__ __forceinline__ float warp_min(float v) {
    #pragma unroll
    for (int o = 16; o; o >>= 1) v = fminf(v, __shfl_xor_sync(0xffffffffu, v, o));
    return v;
}

// ---------------- init ----------------
__global__ void k_init(const float* __restrict__ in1, const float* __restrict__ in2) {
    int idx = blockIdx.x * blockDim.x + threadIdx.x;   // over kB*kN
    if (idx < kB * kN) {
        int b = idx / kN, n = idx % kN;
        const float* p1 = in1 + (size_t)idx * 3;
        const float* p2 = in2 + (size_t)idx * 3;
        float x1 = p1[0], y1 = p1[1], z1 = p1[2];
        float x2 = p2[0], y2 = p2[1], z2 = p2[2];
        g_P1[b][n] = make_float4(x1, y1, z1, x1 * x1 + y1 * y1 + z1 * z1);
        g_P2[b][n] = make_float4(x2, y2, z2, x2 * x2 + y2 * y2 + z2 * z2);
        g_remainL[b][n] = 1.0f;
        g_remainR[b][n] = 1.0f;
        g_remReff[b][n] = 0.0f;
        g_rowscale[b][n] = 0.0f;
    }
    if (idx < kB * (kM / MTILE)) g_costPart[idx / (kM / MTILE)][idx % (kM / MTILE)] = 0.0f;
}

// ---------------- rowmin (one-time) ----------------
__global__ void __launch_bounds__(256) k_rowmin() {
    __shared__ float4 s2[kM];
    int cta = blockIdx.x;
    int b = cta / (kN / ROWS_PER_CTA);
    int rowbase = (cta % (kN / ROWS_PER_CTA)) * ROWS_PER_CTA;
    for (int i = threadIdx.x; i < kM; i += 256) s2[i] = g_P2[b][i];
    __syncthreads();
    int warp = threadIdx.x >> 5, lane = threadIdx.x & 31;
    float x1[RPW], y1[RPW], z1[RPW], mn[RPW];
    #pragma unroll
    for (int r = 0; r < RPW; r++) {
        float4 p = g_P1[b][rowbase + warp * RPW + r];
        x1[r] = p.x; y1[r] = p.y; z1[r] = p.z; mn[r] = 3.4e38f;
    }
    for (int m = lane; m < kM; m += 32) {
        float4 q = s2[m];
        #pragma unroll
        for (int r = 0; r < RPW; r++) {
            float dx = x1[r] - q.x, dy = y1[r] - q.y, dz = z1[r] - q.z;
            mn[r] = fminf(mn[r], dx * dx + dy * dy + dz * dz);
        }
    }
    #pragma unroll
    for (int r = 0; r < RPW; r++) {
        float v = warp_min(mn[r]);
        if (lane == 0) g_rowmin[b][rowbase + warp * RPW + r] = v;
    }
}

// ---------------- one-time distance table: d16[b][n/2][m] = fp16 sqrt(d2) ----------------
__global__ void __launch_bounds__(256) k_dprep() {
    __shared__ float4 s1[NCHUNK];
    int cta = blockIdx.x;
    int b = cta / ((kM / MTILE) * NCHUNKS);
    int rem = cta % ((kM / MTILE) * NCHUNKS);
    int mtile = rem / NCHUNKS;
    int chunk = rem % NCHUNKS;
    int nbase = chunk * NCHUNK;
    s1[threadIdx.x] = g_P1[b][nbase + threadIdx.x];
    __syncthreads();
    int m = mtile * MTILE + threadIdx.x;
    float4 q = g_P2[b][m];
    int jbase = nbase >> 1;
    #pragma unroll 4
    for (int j = 0; j < NCHUNK / 2; j++) {
        float4 p0 = s1[2 * j], p1 = s1[2 * j + 1];
        float dx0 = p0.x - q.x, dy0 = p0.y - q.y, dz0 = p0.z - q.z;
        float dx1 = p1.x - q.x, dy1 = p1.y - q.y, dz1 = p1.z - q.z;
        float d0 = sqrt_apx(dx0 * dx0 + dy0 * dy0 + dz0 * dz0);
        float d1 = sqrt_apx(dx1 * dx1 + dy1 * dy1 + dz1 * dz1);
        g_d16[b][jbase + j][m] = __floats2half2_rn(d0, d1);
    }
}

// ---------------- fused pass: C(level j-1) + A(level j) ----------------
// NORMAL (LAST=false): lvl_prev = 4*lvl_cur exactly -> e_prev = (e^2)^2, one ex2/pair.
// LAST   (LAST=true):  level j=9 (cur=0): A is trivial (rowsum = sum remainR), C direct.
template<bool LAST>
__global__ void __launch_bounds__(256) k_fusedAC(float lvl2p, float lvl2c) {
    __shared__ float4 s2[kM];        // (x,y,z, lvlF*|q|^2)
    __shared__ float2 sw[kM];        // (remReff, remainR)
    __shared__ float  s_sumR;
    int cta = blockIdx.x;
    int b = cta / (kN / ROWS_PER_CTA);
    int rowbase = (cta % (kN / ROWS_PER_CTA)) * ROWS_PER_CTA;
    int warp = threadIdx.x >> 5, lane = threadIdx.x & 31;
    float lvlF = LAST ? lvl2p : lvl2c;

    float bx[RPW], by[RPW], bz[RPW], bc[RPW], rsPrev[RPW];
    bool liveA[RPW];
    bool anyA = false, anyC = false;
    #pragma unroll
    for (int r = 0; r < RPW; r++) {
        int n = rowbase + warp * RPW + r;
        float4 p = g_P1[b][n];
        bx[r] = lvlF * -2.0f * p.x;
        by[r] = lvlF * -2.0f * p.y;
        bz[r] = lvlF * -2.0f * p.z;
        bc[r] = lvlF * p.w;
        rsPrev[r] = g_rowscale[b][n];
        liveA[r] = (!LAST) && (lvl2c * g_rowmin[b][n] >= SKIP_X);
        anyA |= liveA[r];
        anyC |= (rsPrev[r] != 0.0f);
    }
    ull bxp[2], byp[2], bzp[2], bcp[2];
    #pragma unroll
    for (int pr = 0; pr < 2; pr++) {
        bxp[pr] = pk(bx[2 * pr], bx[2 * pr + 1]);
        byp[pr] = pk(by[2 * pr], by[2 * pr + 1]);
        bzp[pr] = pk(bz[2 * pr], bz[2 * pr + 1]);
        bcp[pr] = pk(bc[2 * pr], bc[2 * pr + 1]);
    }
    if (LAST && threadIdx.x == 0) {
        float s = 0.0f;
        #pragma unroll
        for (int mt = 0; mt < kM / MTILE; mt++) s += g_sumRPart[b][mt];
        s_sumR = s;
    }
    int ctaAny = __syncthreads_or((anyA || anyC) ? 1 : 0);

    ull accA[2] = {0ull, 0ull}, accC[2] = {0ull, 0ull};   // bit pattern 0 == {0.f,0.f}
    if (ctaAny) {
        for (int i = threadIdx.x; i < kM; i += 256) {
            float4 q = g_P2[b][i];
            q.w *= lvlF;
            s2[i] = q;
            sw[i] = make_float2(g_remReff[b][i], g_remainR[b][i]);
        }
        __syncthreads();
        #pragma unroll 2
        for (int m = lane; m < kM; m += 32) {
            float4 q = s2[m];
            float2 w = sw[m];
            ull qxx = pk(q.x, q.x), qyy = pk(q.y, q.y), qzz = pk(q.z, q.z), qcc = pk(q.w, q.w);
            ull wxx = pk(w.x, w.x), wyy = pk(w.y, w.y);
            #pragma unroll
            for (int pr = 0; pr < 2; pr++) {
                ull a = add2(bcp[pr], qcc);
                a = fma2(bxp[pr], qxx, a);
                a = fma2(byp[pr], qyy, a);
                a = fma2(bzp[pr], qzz, a);
                float2 af = upk(a);
                ull e = pk(ex2f(af.x), ex2f(af.y));
                if (!LAST) {
                    ull e2 = mul2(e, e);
                    ull e4 = mul2(e2, e2);
                    accC[pr] = fma2(e4, wxx, accC[pr]);
                    accA[pr] = fma2(e, wyy, accA[pr]);
                } else {
                    accC[pr] = fma2(e, wxx, accC[pr]);
                }
            }
        }
    }

    #pragma unroll
    for (int r = 0; r < RPW; r++) {
        float2 cpair = upk(accC[r >> 1]);
        float2 apair = upk(accA[r >> 1]);
        float sC = warp_sum((r & 1) ? cpair.y : cpair.x);
        float sA = warp_sum((r & 1) ? apair.y : apair.x);
        if (lane == 0) {
            int n = rowbase + warp * RPW + r;
            float remL = g_remainL[b][n];
            remL = fmaxf(remL - rsPrev[r] * sC, 0.0f);
            g_remainL[b][n] = remL;
            float rs;
            if (LAST)            rs = remL / (s_sumR + 1e-9f);
            else if (liveA[r])   rs = remL / (sA + 1e-9f);
            else                 rs = 0.0f;
            g_rowscale[b][n] = rs;
            float lg = (rs > 0.0f) ? lg2f(rs) : DEAD_LG;
            float l2 = LAST ? 0.0f : lvl2c;
            float4 p = g_P1[b][n];
            g_rowB[b][n] = make_float4(l2 * -2.0f * p.x, l2 * -2.0f * p.y,
                                       l2 * -2.0f * p.z, fmaf(l2, p.w, lg));
        }
    }
}

// ---------------- pass B: column partials; exp folded with log2(rowscale); d from table ----------------
__global__ void __launch_bounds__(256) k_passB(float lvl2) {
    __shared__ float4 sA[NCHUNK / 2];     // (x0,x1,y0,y1) row-pair packed
    __shared__ float4 sB[NCHUNK / 2];     // (z0,z1,c0,c1)
    int cta = blockIdx.x;
    int b = cta / ((kM / MTILE) * NCHUNKS);
    int rem = cta % ((kM / MTILE) * NCHUNKS);
    int mtile = rem / NCHUNKS;
    int chunk = rem % NCHUNKS;
    int nbase = chunk * NCHUNK;

    bool liveT = false;
    if (threadIdx.x < NCHUNK / 2) {
        float4 r0 = g_rowB[b][nbase + 2 * threadIdx.x];
        float4 r1 = g_rowB[b][nbase + 2 * threadIdx.x + 1];
        sA[threadIdx.x] = make_float4(r0.x, r1.x, r0.y, r1.y);
        sB[threadIdx.x] = make_float4(r0.z, r1.z, r0.w, r1.w);
        liveT = (r0.w > -1e29f) || (r1.w > -1e29f);
    }
    int any = __syncthreads_or(liveT ? 1 : 0);
    int m = mtile * MTILE + threadIdx.x;
    if (!any) {
        g_colsum[b][chunk][m] = 0.0f;
        g_colsumd[b][chunk][m] = 0.0f;
        return;
    }
    float4 q = g_P2[b][m];
    float qc = lvl2 * q.w;
    ull qxx = pk(q.x, q.x), qyy = pk(q.y, q.y), qzz = pk(q.z, q.z), qcc = pk(qc, qc);
    const __half2* dp = &g_d16[b][nbase >> 1][m];
    ull cs2 = 0ull, csd2 = 0ull;
    #pragma unroll 4
    for (int j = 0; j < NCHUNK / 2; j++) {
        float4 A = sA[j], Bv = sB[j];
        ull a = add2(pk(Bv.z, Bv.w), qcc);
        a = fma2(pk(A.x, A.y), qxx, a);
        a = fma2(pk(A.z, A.w), qyy, a);
        a = fma2(pk(Bv.x, Bv.y), qzz, a);
        float2 af = upk(a);
        ull e = pk(ex2f(af.x), ex2f(af.y));     // includes rowscale (folded as lg2)
        cs2 = add2(cs2, e);
        float2 df = __half22float2(dp[j * kM]);
        csd2 = fma2(e, pk(df.x, df.y), csd2);
    }
    float2 c = upk(cs2), cd = upk(csd2);
    float remR = g_remainR[b][m];
    g_colsum[b][chunk][m]  = (c.x + c.y) * remR;
    g_colsumd[b][chunk][m] = (cd.x + cd.y) * remR;
}

// ---------------- pass E1: clip, per-tile cost partials, remainR update ----------------
__global__ void __launch_bounds__(256) k_passE1() {
    __shared__ float r1[256], r2[256];
    int b = blockIdx.x / (kM / MTILE);
    int mt = blockIdx.x % (kM / MTILE);
    int m = mt * MTILE + threadIdx.x;
    float cs = 0.0f, csd = 0.0f;
    #pragma unroll
    for (int c = 0; c < NCHUNKS; c++) { cs += g_colsum[b][c][m]; csd += g_colsumd[b][c][m]; }
    float rr = g_remainR[b][m];
    float csc = fminf(rr / (cs + 1e-9f), 1.0f);
    g_remReff[b][m] = rr * csc;
    float nr = fmaxf(rr - cs * csc, 0.0f);
    g_remainR[b][m] = nr;
    r1[threadIdx.x] = csd * csc;
    r2[threadIdx.x] = nr;
    __syncthreads();
    #pragma unroll
    for (int s = 128; s > 0; s >>= 1) {
        if (threadIdx.x < s) {
            r1[threadIdx.x] += r1[threadIdx.x + s];
            r2[threadIdx.x] += r2[threadIdx.x + s];
        }
        __syncthreads();
    }
    if (threadIdx.x == 0) {
        g_costPart[b][mt] += r1[0];
        g_sumRPart[b][mt] = r2[0];
    }
}

// ---------------- final: reduce cost partials into out ----------------
__global__ void k_final(float* __restrict__ out) {
    int b = blockIdx.x;
    int lane = threadIdx.x;
    float v = (lane < kM / MTILE) ? g_costPart[b][lane] : 0.0f;
    v = warp_sum(v);
    if (lane == 0) out[b] = v;
}

// ---------------- launch ----------------
extern "C" void kernel_launch(void* const* d_in, const int* in_sizes, int n_in,
                              void* d_out, int out_size) {
    const float* in1 = (const float*)d_in[0];
    const float* in2 = (const float*)d_in[1];
    float* out = (float*)d_out;

    static const float levels[10] = {
        -16384.f, -4096.f, -1024.f, -256.f, -64.f, -16.f, -4.f, -1.f, -0.25f, 0.f
    };

    k_init<<<(kB * kN + 255) / 256, 256>>>(in1, in2);
    k_rowmin<<<GRID_AC, 256>>>();
    k_dprep<<<GRID_B, 256>>>();
    float lp = 0.0f;
    for (int j = 0; j < 10; j++) {
        float lc = levels[j] * LOG2E;
        if (j < 9) k_fusedAC<false><<<GRID_AC, 256>>>(lp, lc);
        else       k_fusedAC<true ><<<GRID_AC, 256>>>(lp, lc);
        k_passB<<<GRID_B, 256>>>(lc);
        k_passE1<<<kB * (kM / MTILE), 256>>>();
        lp = lc;
    }
    k_final<<<kB, 32>>>(out);
}

// round 9
// speedup vs baseline: 2.4610x; 1.0006x over previous
#include <cuda_runtime.h>
#include <cuda_fp16.h>

// Problem shape (fixed by the dataset): B=8, N=M=2048, 3-D points.
#define kB 8
#define kN 2048
#define kM 2048

// Fused A+C geometry: 256 threads = 8 warps, 2 rows/warp -> 16 rows/CTA
#define RPW 2
#define ROWS_PER_CTA 16
#define GRID_AC (kB * kN / ROWS_PER_CTA)            // 1024

// Pass B / dprep geometry: thread-per-column tile of 256, n chunks of 256
#define MTILE 256
#define NCHUNK 256
#define NCHUNKS (kN / NCHUNK)                       // 8
#define GRID_B (kB * (kM / MTILE) * NCHUNKS)        // 512

#define SKIP_X (-60.0f)
#define LOG2E 1.4426950408889634f
#define DEAD_LG (-1e30f)     // stands in for log2(0); ex2 underflows to exact 0

typedef unsigned long long ull;

// ---------------- scratch (static __device__, no allocation) ----------------
__device__ float4  g_P1[kB][kN];                // (x,y,z,|p|^2)
__device__ float4  g_P2[kB][kM];                // (x,y,z,|q|^2)
__device__ float   g_rowmin[kB][kN];
__device__ float   g_rowscale[kB][kN];
__device__ float4  g_rowB[kB][kN];              // (l2*-2x, l2*-2y, l2*-2z, l2*|p|^2 + lg2(rs))
__device__ float   g_remainL[kB][kN];
__device__ float   g_remainR[kB][kM];
__device__ float   g_remReff[kB][kM];
__device__ float   g_colsum[kB][NCHUNKS][kM];
__device__ float   g_colsumd[kB][NCHUNKS][kM];
__device__ float   g_costPart[kB][kM / MTILE];
__device__ float   g_sumRPart[kB][kM / MTILE];
__device__ __half2 g_d16[kB][kN / 2][kM];       // 64 MB distance table, pair over n

// ---------------- helpers ----------------
__device__ __forceinline__ float ex2f(float x) {
    float r; asm("ex2.approx.f32 %0, %1;" : "=f"(r) : "f"(x)); return r;
}
__device__ __forceinline__ float lg2f(float x) {
    float r; asm("lg2.approx.f32 %0, %1;" : "=f"(r) : "f"(x)); return r;
}
__device__ __forceinline__ float sqrt_apx(float x) {
    float r; asm("sqrt.approx.f32 %0, %1;" : "=f"(r) : "f"(x)); return r;
}
__device__ __forceinline__ ull pk(float lo, float hi) {
    ull r; asm("mov.b64 %0, {%1, %2};" : "=l"(r) : "f"(lo), "f"(hi)); return r;
}
__device__ __forceinline__ float2 upk(ull v) {
    float lo, hi; asm("mov.b64 {%0, %1}, %2;" : "=f"(lo), "=f"(hi) : "l"(v));
    return make_float2(lo, hi);
}
__device__ __forceinline__ ull fma2(ull a, ull b, ull c) {
    ull r; asm("fma.rn.f32x2 %0, %1, %2, %3;" : "=l"(r) : "l"(a), "l"(b), "l"(c)); return r;
}
__device__ __forceinline__ ull add2(ull a, ull b) {
    ull r; asm("add.rn.f32x2 %0, %1, %2;" : "=l"(r) : "l"(a), "l"(b)); return r;
}
__device__ __forceinline__ ull mul2(ull a, ull b) {
    ull r; asm("mul.rn.f32x2 %0, %1, %2;" : "=l"(r) : "l"(a), "l"(b)); return r;
}
__device__ __forceinline__ float warp_sum(float v) {
    #pragma unroll
    for (int o = 16; o; o >>= 1) v += __shfl_xor_sync(0xffffffffu, v, o);
    return v;
}
__device__ __forceinline__ float warp_min(float v) {
    #pragma unroll
    for (int o = 16; o; o >>= 1) v = fminf(v, __shfl_xor_sync(0xffffffffu, v, o));
    return v;
}

// ---------------- init ----------------
__global__ void k_init(const float* __restrict__ in1, const float* __restrict__ in2) {
    int idx = blockIdx.x * blockDim.x + threadIdx.x;   // over kB*kN
    if (idx < kB * kN) {
        int b = idx / kN, n = idx % kN;
        const float* p1 = in1 + (size_t)idx * 3;
        const float* p2 = in2 + (size_t)idx * 3;
        float x1 = p1[0], y1 = p1[1], z1 = p1[2];
        float x2 = p2[0], y2 = p2[1], z2 = p2[2];
        g_P1[b][n] = make_float4(x1, y1, z1, x1 * x1 + y1 * y1 + z1 * z1);
        g_P2[b][n] = make_float4(x2, y2, z2, x2 * x2 + y2 * y2 + z2 * z2);
        g_remainL[b][n] = 1.0f;
        g_remainR[b][n] = 1.0f;
        g_remReff[b][n] = 0.0f;
        g_rowscale[b][n] = 0.0f;
    }
    if (idx < kB * (kM / MTILE)) g_costPart[idx / (kM / MTILE)][idx % (kM / MTILE)] = 0.0f;
}

// ---------------- rowmin (one-time) ----------------
__global__ void __launch_bounds__(256) k_rowmin() {
    __shared__ float4 s2[kM];
    int cta = blockIdx.x;                                  // over kB * kN/32
    int b = cta / (kN / 32);
    int rowbase = (cta % (kN / 32)) * 32;
    for (int i = threadIdx.x; i < kM; i += 256) s2[i] = g_P2[b][i];
    __syncthreads();
    int warp = threadIdx.x >> 5, lane = threadIdx.x & 31;
    float x1[4], y1[4], z1[4], mn[4];
    #pragma unroll
    for (int r = 0; r < 4; r++) {
        float4 p = g_P1[b][rowbase + warp * 4 + r];
        x1[r] = p.x; y1[r] = p.y; z1[r] = p.z; mn[r] = 3.4e38f;
    }
    for (int m = lane; m < kM; m += 32) {
        float4 q = s2[m];
        #pragma unroll
        for (int r = 0; r < 4; r++) {
            float dx = x1[r] - q.x, dy = y1[r] - q.y, dz = z1[r] - q.z;
            mn[r] = fminf(mn[r], dx * dx + dy * dy + dz * dz);
        }
    }
    #pragma unroll
    for (int r = 0; r < 4; r++) {
        float v = warp_min(mn[r]);
        if (lane == 0) g_rowmin[b][rowbase + warp * 4 + r] = v;
    }
}

// ---------------- one-time distance table: d16[b][n/2][m] = fp16 sqrt(d2) ----------------
__global__ void __launch_bounds__(256) k_dprep() {
    __shared__ float4 s1[NCHUNK];
    int cta = blockIdx.x;
    int b = cta / ((kM / MTILE) * NCHUNKS);
    int rem = cta % ((kM / MTILE) * NCHUNKS);
    int mtile = rem / NCHUNKS;
    int chunk = rem % NCHUNKS;
    int nbase = chunk * NCHUNK;
    s1[threadIdx.x] = g_P1[b][nbase + threadIdx.x];
    __syncthreads();
    int m = mtile * MTILE + threadIdx.x;
    float4 q = g_P2[b][m];
    int jbase = nbase >> 1;
    #pragma unroll 4
    for (int j = 0; j < NCHUNK / 2; j++) {
        float4 p0 = s1[2 * j], p1 = s1[2 * j + 1];
        float dx0 = p0.x - q.x, dy0 = p0.y - q.y, dz0 = p0.z - q.z;
        float dx1 = p1.x - q.x, dy1 = p1.y - q.y, dz1 = p1.z - q.z;
        float d0 = sqrt_apx(dx0 * dx0 + dy0 * dy0 + dz0 * dz0);
        float d1 = sqrt_apx(dx1 * dx1 + dy1 * dy1 + dz1 * dz1);
        g_d16[b][jbase + j][m] = __floats2half2_rn(d0, d1);
    }
}

// ---------------- fused pass: C(level j-1) + A(level j) ----------------
// NORMAL (LAST=false): lvl_prev = 4*lvl_cur exactly -> e_prev = (e^2)^2, one ex2/elem.
// LAST   (LAST=true):  level j=9 (cur=0): A trivial (rowsum = sum remainR), C direct.
// m-pair packed smem: ulonglong2 loads give ready f32x2 operands, zero per-iter movs.
template<bool LAST>
__global__ void __launch_bounds__(256) k_fusedAC(float lvl2p, float lvl2c) {
    __shared__ float4 s_xy[kM / 2];   // (x0,x1,y0,y1)           16 KB
    __shared__ float4 s_zc[kM / 2];   // (z0,z1,lF*c0,lF*c1)     16 KB
    __shared__ float4 s_w [kM / 2];   // (rf0,rf1,rr0,rr1)       16 KB
    __shared__ float  s_sumR;
    int cta = blockIdx.x;
    int b = cta / (kN / ROWS_PER_CTA);
    int rowbase = (cta % (kN / ROWS_PER_CTA)) * ROWS_PER_CTA;
    int warp = threadIdx.x >> 5, lane = threadIdx.x & 31;
    float lvlF = LAST ? lvl2p : lvl2c;

    // per-warp row constants, duplicated-packed ONCE
    ull bx2[RPW], by2[RPW], bz2[RPW], bc2[RPW];
    float rsPrev[RPW];
    bool liveA[RPW];
    bool anyA = false, anyC = false;
    #pragma unroll
    for (int r = 0; r < RPW; r++) {
        int n = rowbase + warp * RPW + r;
        float4 p = g_P1[b][n];
        float bx = lvlF * -2.0f * p.x, by = lvlF * -2.0f * p.y;
        float bz = lvlF * -2.0f * p.z, bc = lvlF * p.w;
        bx2[r] = pk(bx, bx); by2[r] = pk(by, by);
        bz2[r] = pk(bz, bz); bc2[r] = pk(bc, bc);
        rsPrev[r] = g_rowscale[b][n];
        liveA[r] = (!LAST) && (lvl2c * g_rowmin[b][n] >= SKIP_X);
        anyA |= liveA[r];
        anyC |= (rsPrev[r] != 0.0f);
    }
    if (LAST && threadIdx.x == 0) {
        float s = 0.0f;
        #pragma unroll
        for (int mt = 0; mt < kM / MTILE; mt++) s += g_sumRPart[b][mt];
        s_sumR = s;
    }
    int ctaAny = __syncthreads_or((anyA || anyC) ? 1 : 0);

    ull accA[RPW] = {0ull, 0ull}, accC[RPW] = {0ull, 0ull};
    if (ctaAny) {
        for (int j = threadIdx.x; j < kM / 2; j += 256) {
            float4 qa = g_P2[b][2 * j], qb = g_P2[b][2 * j + 1];
            s_xy[j] = make_float4(qa.x, qb.x, qa.y, qb.y);
            s_zc[j] = make_float4(qa.z, qb.z, lvlF * qa.w, lvlF * qb.w);
            s_w [j] = make_float4(g_remReff[b][2 * j], g_remReff[b][2 * j + 1],
                                  g_remainR[b][2 * j], g_remainR[b][2 * j + 1]);
        }
        __syncthreads();
        #pragma unroll 2
        for (int j = lane; j < kM / 2; j += 32) {
            ulonglong2 xy = *reinterpret_cast<const ulonglong2*>(&s_xy[j]);
            ulonglong2 zc = *reinterpret_cast<const ulonglong2*>(&s_zc[j]);
            ulonglong2 w  = *reinterpret_cast<const ulonglong2*>(&s_w [j]);
            #pragma unroll
            for (int r = 0; r < RPW; r++) {
                ull a = add2(bc2[r], zc.y);
                a = fma2(bx2[r], xy.x, a);
                a = fma2(by2[r], xy.y, a);
                a = fma2(bz2[r], zc.x, a);
                float2 af = upk(a);
                ull e = pk(ex2f(af.x), ex2f(af.y));
                if (!LAST) {
                    ull e2 = mul2(e, e);
                    ull e4 = mul2(e2, e2);
                    accC[r] = fma2(e4, w.x, accC[r]);
                    accA[r] = fma2(e, w.y, accA[r]);
                } else {
                    accC[r] = fma2(e, w.x, accC[r]);
                }
            }
        }
    }

    #pragma unroll
    for (int r = 0; r < RPW; r++) {
        float2 c2 = upk(accC[r]);
        float2 a2 = upk(accA[r]);
        float sC = warp_sum(c2.x + c2.y);
        float sA = warp_sum(a2.x + a2.y);
        if (lane == 0) {
            int n = rowbase + warp * RPW + r;
            float remL = g_remainL[b][n];
            remL = fmaxf(remL - rsPrev[r] * sC, 0.0f);
            g_remainL[b][n] = remL;
            float rs;
            if (LAST)            rs = remL / (s_sumR + 1e-9f);
            else if (liveA[r])   rs = remL / (sA + 1e-9f);
            else                 rs = 0.0f;
            g_rowscale[b][n] = rs;
            float lg = (rs > 0.0f) ? lg2f(rs) : DEAD_LG;
            float l2 = LAST ? 0.0f : lvl2c;
            float4 p = g_P1[b][n];
            g_rowB[b][n] = make_float4(l2 * -2.0f * p.x, l2 * -2.0f * p.y,
                                       l2 * -2.0f * p.z, fmaf(l2, p.w, lg));
        }
    }
}

// ---------------- pass B: column partials; rowscale folded as lg2; d from table ----------------
__global__ void __launch_bounds__(256) k_passB(float lvl2) {
    __shared__ float4 sXY[NCHUNK / 2];   // (x0,x1,y0,y1) of rowB, row-pair packed
    __shared__ float4 sZC[NCHUNK / 2];   // (z0,z1,c0,c1)
    int cta = blockIdx.x;
    int b = cta / ((kM / MTILE) * NCHUNKS);
    int rem = cta % ((kM / MTILE) * NCHUNKS);
    int mtile = rem / NCHUNKS;
    int chunk = rem % NCHUNKS;
    int nbase = chunk * NCHUNK;

    bool liveT = false;
    if (threadIdx.x < NCHUNK / 2) {
        float4 r0 = g_rowB[b][nbase + 2 * threadIdx.x];
        float4 r1 = g_rowB[b][nbase + 2 * threadIdx.x + 1];
        sXY[threadIdx.x] = make_float4(r0.x, r1.x, r0.y, r1.y);
        sZC[threadIdx.x] = make_float4(r0.z, r1.z, r0.w, r1.w);
        liveT = (r0.w > -1e29f) || (r1.w > -1e29f);
    }
    int any = __syncthreads_or(liveT ? 1 : 0);
    int m = mtile * MTILE + threadIdx.x;
    if (!any) {
        g_colsum[b][chunk][m] = 0.0f;
        g_colsumd[b][chunk][m] = 0.0f;
        return;
    }
    float4 q = g_P2[b][m];
    float qc = lvl2 * q.w;
    ull qxx = pk(q.x, q.x), qyy = pk(q.y, q.y), qzz = pk(q.z, q.z), qcc = pk(qc, qc);
    const __half2* dp = &g_d16[b][nbase >> 1][m];
    ull cs2 = 0ull, csd2 = 0ull;
    #pragma unroll 4
    for (int j = 0; j < NCHUNK / 2; j++) {
        ulonglong2 xy = *reinterpret_cast<const ulonglong2*>(&sXY[j]);
        ulonglong2 zc = *reinterpret_cast<const ulonglong2*>(&sZC[j]);
        ull a = add2(zc.y, qcc);
        a = fma2(xy.x, qxx, a);
        a = fma2(xy.y, qyy, a);
        a = fma2(zc.x, qzz, a);
        float2 af = upk(a);
        ull e = pk(ex2f(af.x), ex2f(af.y));     // includes rowscale (folded as lg2)
        cs2 = add2(cs2, e);
        float2 df = __half22float2(dp[j * kM]);
        csd2 = fma2(e, pk(df.x, df.y), csd2);
    }
    float2 c = upk(cs2), cd = upk(csd2);
    float remR = g_remainR[b][m];
    g_colsum[b][chunk][m]  = (c.x + c.y) * remR;
    g_colsumd[b][chunk][m] = (cd.x + cd.y) * remR;
}

// ---------------- pass E1: clip, per-tile cost partials, remainR update ----------------
__global__ void __launch_bounds__(256) k_passE1() {
    __shared__ float r1[256], r2[256];
    int b = blockIdx.x / (kM / MTILE);
    int mt = blockIdx.x % (kM / MTILE);
    int m = mt * MTILE + threadIdx.x;
    float cs = 0.0f, csd = 0.0f;
    #pragma unroll
    for (int c = 0; c < NCHUNKS; c++) { cs += g_colsum[b][c][m]; csd += g_colsumd[b][c][m]; }
    float rr = g_remainR[b][m];
    float csc = fminf(rr / (cs + 1e-9f), 1.0f);
    g_remReff[b][m] = rr * csc;
    float nr = fmaxf(rr - cs * csc, 0.0f);
    g_remainR[b][m] = nr;
    r1[threadIdx.x] = csd * csc;
    r2[threadIdx.x] = nr;
    __syncthreads();
    #pragma unroll
    for (int s = 128; s > 0; s >>= 1) {
        if (threadIdx.x < s) {
            r1[threadIdx.x] += r1[threadIdx.x + s];
            r2[threadIdx.x] += r2[threadIdx.x + s];
        }
        __syncthreads();
    }
    if (threadIdx.x == 0) {
        g_costPart[b][mt] += r1[0];
        g_sumRPart[b][mt] = r2[0];
    }
}

// ---------------- final: reduce cost partials into out ----------------
__global__ void k_final(float* __restrict__ out) {
    int b = blockIdx.x;
    int lane = threadIdx.x;
    float v = (lane < kM / MTILE) ? g_costPart[b][lane] : 0.0f;
    v = warp_sum(v);
    if (lane == 0) out[b] = v;
}

// ---------------- launch ----------------
extern "C" void kernel_launch(void* const* d_in, const int* in_sizes, int n_in,
                              void* d_out, int out_size) {
    const float* in1 = (const float*)d_in[0];
    const float* in2 = (const float*)d_in[1];
    float* out = (float*)d_out;

    static const float levels[10] = {
        -16384.f, -4096.f, -1024.f, -256.f, -64.f, -16.f, -4.f, -1.f, -0.25f, 0.f
    };

    k_init<<<(kB * kN + 255) / 256, 256>>>(in1, in2);
    k_rowmin<<<kB * (kN / 32), 256>>>();
    k_dprep<<<GRID_B, 256>>>();
    float lp = 0.0f;
    for (int j = 0; j < 10; j++) {
        float lc = levels[j] * LOG2E;
        if (j < 9) k_fusedAC<false><<<GRID_AC, 256>>>(lp, lc);
        else       k_fusedAC<true ><<<GRID_AC, 256>>>(lp, lc);
        k_passB<<<GRID_B, 256>>>(lc);
        k_passE1<<<kB * (kM / MTILE), 256>>>();
        lp = lc;
    }
    k_final<<<kB, 32>>>(out);
}

// round 10
// speedup vs baseline: 2.5067x; 1.0186x over previous
#include <cuda_runtime.h>
#include <cuda_fp16.h>

// Problem shape (fixed by the dataset): B=8, N=M=2048, 3-D points.
#define kB 8
#define kN 2048
#define kM 2048

// Fused A+C geometry: 256 threads = 8 warps; one ROW PER LANE (32 rows/CTA),
// each warp sweeps a disjoint 128-m-pair segment with broadcast smem loads.
#define GRID_AC (kB * kN / 32)                      // 512

// Pass B+E geometry: thread-per-column tile of 256, n chunks of 256
#define MTILE 256
#define NCHUNK 256
#define NCHUNKS (kN / NCHUNK)                       // 8
#define NMT (kM / MTILE)                            // 8
#define GRID_B (kB * NMT * NCHUNKS)                 // 512

#define SKIP_X (-60.0f)
#define LOG2E 1.4426950408889634f
#define DEAD_LG (-1e30f)     // stands in for log2(0); ex2 underflows to exact 0

typedef unsigned long long ull;

// ---------------- scratch (static __device__, no allocation) ----------------
__device__ float4  g_P1[kB][kN];                // (x,y,z,|p|^2)
__device__ float4  g_P2[kB][kM];                // (x,y,z,|q|^2)
__device__ float   g_rowmin[kB][kN];
__device__ float   g_rowscale[kB][kN];
__device__ float4  g_rowB[kB][kN];              // (l2*-2x, l2*-2y, l2*-2z, l2*|p|^2 + lg2(rs))
__device__ float   g_remainL[kB][kN];
__device__ float   g_remainR[kB][kM];
__device__ float   g_remReff[kB][kM];
__device__ float   g_colsum[kB][NCHUNKS][kM];
__device__ float   g_colsumd[kB][NCHUNKS][kM];
__device__ float   g_costPart[kB][NMT];
__device__ float   g_sumRPart[kB][NMT];
__device__ unsigned int g_ticket[kB][NMT];      // last-CTA election for fused E
__device__ __half2 g_d16[kB][kN / 2][kM];       // 64 MB distance table, pair over n

// ---------------- helpers ----------------
__device__ __forceinline__ float ex2f(float x) {
    float r; asm("ex2.approx.f32 %0, %1;" : "=f"(r) : "f"(x)); return r;
}
__device__ __forceinline__ float lg2f(float x) {
    float r; asm("lg2.approx.f32 %0, %1;" : "=f"(r) : "f"(x)); return r;
}
__device__ __forceinline__ float sqrt_apx(float x) {
    float r; asm("sqrt.approx.f32 %0, %1;" : "=f"(r) : "f"(x)); return r;
}
__device__ __forceinline__ ull pk(float lo, float hi) {
    ull r; asm("mov.b64 %0, {%1, %2};" : "=l"(r) : "f"(lo), "f"(hi)); return r;
}
__device__ __forceinline__ float2 upk(ull v) {
    float lo, hi; asm("mov.b64 {%0, %1}, %2;" : "=f"(lo), "=f"(hi) : "l"(v));
    return make_float2(lo, hi);
}
__device__ __forceinline__ ull fma2(ull a, ull b, ull c) {
    ull r; asm("fma.rn.f32x2 %0, %1, %2, %3;" : "=l"(r) : "l"(a), "l"(b), "l"(c)); return r;
}
__device__ __forceinline__ ull add2(ull a, ull b) {
    ull r; asm("add.rn.f32x2 %0, %1, %2;" : "=l"(r) : "l"(a), "l"(b)); return r;
}
__device__ __forceinline__ ull mul2(ull a, ull b) {
    ull r; asm("mul.rn.f32x2 %0, %1, %2;" : "=l"(r) : "l"(a), "l"(b)); return r;
}
__device__ __forceinline__ float warp_sum(float v) {
    #pragma unroll
    for (int o = 16; o; o >>= 1) v += __shfl_xor_sync(0xffffffffu, v, o);
    return v;
}
__device__ __forceinline__ float warp_min(float v) {
    #pragma unroll
    for (int o = 16; o; o >>= 1) v = fminf(v, __shfl_xor_sync(0xffffffffu, v, o));
    return v;
}

// ---------------- init ----------------
__global__ void k_init(const float* __restrict__ in1, const float* __restrict__ in2) {
    int idx = blockIdx.x * blockDim.x + threadIdx.x;   // over kB*kN
    if (idx < kB * kN) {
        int b = idx / kN, n = idx % kN;
        const float* p1 = in1 + (size_t)idx * 3;
        const float* p2 = in2 + (size_t)idx * 3;
        float x1 = p1[0], y1 = p1[1], z1 = p1[2];
        float x2 = p2[0], y2 = p2[1], z2 = p2[2];
        g_P1[b][n] = make_float4(x1, y1, z1, x1 * x1 + y1 * y1 + z1 * z1);
        g_P2[b][n] = make_float4(x2, y2, z2, x2 * x2 + y2 * y2 + z2 * z2);
        g_remainL[b][n] = 1.0f;
        g_remainR[b][n] = 1.0f;
        g_remReff[b][n] = 0.0f;
        g_rowscale[b][n] = 0.0f;
    }
    if (idx < kB * NMT) {
        g_costPart[idx / NMT][idx % NMT] = 0.0f;
        g_ticket[idx / NMT][idx % NMT] = 0u;
    }
}

// ---------------- rowmin (one-time) ----------------
__global__ void __launch_bounds__(256) k_rowmin() {
    __shared__ float4 s2[kM];
    int cta = blockIdx.x;                                  // over kB * kN/32
    int b = cta / (kN / 32);
    int rowbase = (cta % (kN / 32)) * 32;
    for (int i = threadIdx.x; i < kM; i += 256) s2[i] = g_P2[b][i];
    __syncthreads();
    int warp = threadIdx.x >> 5, lane = threadIdx.x & 31;
    float4 p = g_P1[b][rowbase + lane];
    float mn = 3.4e38f;
    for (int m = warp * (kM / 8); m < (warp + 1) * (kM / 8); m++) {
        float4 q = s2[m];                                   // broadcast
        float dx = p.x - q.x, dy = p.y - q.y, dz = p.z - q.z;
        mn = fminf(mn, dx * dx + dy * dy + dz * dz);
    }
    __shared__ float smn[8][33];
    smn[warp][lane] = mn;
    __syncthreads();
    if (warp == 0) {
        float v = smn[0][lane];
        #pragma unroll
        for (int w = 1; w < 8; w++) v = fminf(v, smn[w][lane]);
        g_rowmin[b][rowbase + lane] = v;
    }
}

// ---------------- one-time distance table: d16[b][n/2][m] = fp16 sqrt(d2) ----------------
__global__ void __launch_bounds__(256) k_dprep() {
    __shared__ float4 s1[NCHUNK];
    int cta = blockIdx.x;
    int b = cta / (NMT * NCHUNKS);
    int rem = cta % (NMT * NCHUNKS);
    int mtile = rem / NCHUNKS;
    int chunk = rem % NCHUNKS;
    int nbase = chunk * NCHUNK;
    s1[threadIdx.x] = g_P1[b][nbase + threadIdx.x];
    __syncthreads();
    int m = mtile * MTILE + threadIdx.x;
    float4 q = g_P2[b][m];
    int jbase = nbase >> 1;
    #pragma unroll 4
    for (int j = 0; j < NCHUNK / 2; j++) {
        float4 p0 = s1[2 * j], p1 = s1[2 * j + 1];
        float dx0 = p0.x - q.x, dy0 = p0.y - q.y, dz0 = p0.z - q.z;
        float dx1 = p1.x - q.x, dy1 = p1.y - q.y, dz1 = p1.z - q.z;
        float d0 = sqrt_apx(dx0 * dx0 + dy0 * dy0 + dz0 * dz0);
        float d1 = sqrt_apx(dx1 * dx1 + dy1 * dy1 + dz1 * dz1);
        g_d16[b][jbase + j][m] = __floats2half2_rn(d0, d1);
    }
}

// ---------------- fused pass: C(level j-1) + A(level j), broadcast form ----------------
// One row per lane; warp w sweeps m-pairs [w*128, (w+1)*128): all smem loads are
// warp-broadcast. NORMAL: lvl_prev = 4*lvl_cur exactly -> e_prev = (e^2)^2.
// LAST (j=9, cur level 0): A trivial (rowsum = sum remainR), C direct at lvl2p.
template<bool LAST>
__global__ void __launch_bounds__(256) k_fusedAC(float lvl2p, float lvl2c) {
    __shared__ float4 s_xy[kM / 2];   // (x0,x1,y0,y1)           16 KB
    __shared__ float4 s_zc[kM / 2];   // (z0,z1,lF*c0,lF*c1)     16 KB
    __shared__ float4 s_w [kM / 2];   // (rf0,rf1,rr0,rr1)       16 KB
    __shared__ float  sA_p[8][33];
    __shared__ float  sC_p[8][33];
    __shared__ float  s_sumR;
    int cta = blockIdx.x;
    int b = cta / (kN / 32);
    int rowbase = (cta % (kN / 32)) * 32;
    int warp = threadIdx.x >> 5, lane = threadIdx.x & 31;
    int n = rowbase + lane;                       // this lane's row (same in every warp)
    float lvlF = LAST ? lvl2p : lvl2c;

    float4 p = g_P1[b][n];
    float rsPrev = g_rowscale[b][n];
    bool liveA = (!LAST) && (lvl2c * g_rowmin[b][n] >= SKIP_X);

    if (LAST && threadIdx.x == 0) {
        float s = 0.0f;
        #pragma unroll
        for (int mt = 0; mt < NMT; mt++) s += g_sumRPart[b][mt];
        s_sumR = s;
    }
    int ctaAny = __syncthreads_or((liveA || (rsPrev != 0.0f)) ? 1 : 0);

    if (ctaAny) {
        for (int j = threadIdx.x; j < kM / 2; j += 256) {
            float4 qa = g_P2[b][2 * j], qb = g_P2[b][2 * j + 1];
            s_xy[j] = make_float4(qa.x, qb.x, qa.y, qb.y);
            s_zc[j] = make_float4(qa.z, qb.z, lvlF * qa.w, lvlF * qb.w);
            s_w [j] = make_float4(g_remReff[b][2 * j], g_remReff[b][2 * j + 1],
                                  g_remainR[b][2 * j], g_remainR[b][2 * j + 1]);
        }
        __syncthreads();
        float bxf = lvlF * -2.0f * p.x, byf = lvlF * -2.0f * p.y;
        float bzf = lvlF * -2.0f * p.z, bcf = lvlF * p.w;
        ull bx2 = pk(bxf, bxf), by2 = pk(byf, byf), bz2 = pk(bzf, bzf), bc2 = pk(bcf, bcf);
        ull accA = 0ull, accC = 0ull;
        int j0 = warp * (kM / 16);                // 128 m-pairs per warp
        #pragma unroll 4
        for (int j = j0; j < j0 + kM / 16; j++) {
            ulonglong2 xy = *reinterpret_cast<const ulonglong2*>(&s_xy[j]);   // broadcast
            ulonglong2 zc = *reinterpret_cast<const ulonglong2*>(&s_zc[j]);
            ulonglong2 w  = *reinterpret_cast<const ulonglong2*>(&s_w [j]);
            ull a = add2(bc2, zc.y);
            a = fma2(bx2, xy.x, a);
            a = fma2(by2, xy.y, a);
            a = fma2(bz2, zc.x, a);
            float2 af = upk(a);
            ull e = pk(ex2f(af.x), ex2f(af.y));
            if (!LAST) {
                ull e2 = mul2(e, e);
                ull e4 = mul2(e2, e2);
                accC = fma2(e4, w.x, accC);
                accA = fma2(e, w.y, accA);
            } else {
                accC = fma2(e, w.x, accC);
            }
        }
        float2 a2 = upk(accA), c2 = upk(accC);
        sA_p[warp][lane] = a2.x + a2.y;
        sC_p[warp][lane] = c2.x + c2.y;
    } else {
        sA_p[warp][lane] = 0.0f;
        sC_p[warp][lane] = 0.0f;
    }
    __syncthreads();

    if (warp == 0) {                              // lane == row; p/rsPrev/liveA are lane-local
        float sA = 0.0f, sC = 0.0f;
        #pragma unroll
        for (int w = 0; w < 8; w++) { sA += sA_p[w][lane]; sC += sC_p[w][lane]; }
        float remL = g_remainL[b][n];
        remL = fmaxf(remL - rsPrev * sC, 0.0f);
        g_remainL[b][n] = remL;
        float rs;
        if (LAST)            rs = remL / (s_sumR + 1e-9f);
        else if (liveA)      rs = remL / (sA + 1e-9f);
        else                 rs = 0.0f;
        g_rowscale[b][n] = rs;
        float lg = (rs > 0.0f) ? lg2f(rs) : DEAD_LG;
        float l2 = LAST ? 0.0f : lvl2c;
        g_rowB[b][n] = make_float4(l2 * -2.0f * p.x, l2 * -2.0f * p.y,
                                   l2 * -2.0f * p.z, fmaf(l2, p.w, lg));
    }
}

// ---------------- fused pass B + E: column partials; last CTA per mtile does the
// clip / cost / remainR update (deterministic: fixed-order sums; ticket elects worker)
__global__ void __launch_bounds__(256) k_passBE(float lvl2) {
    __shared__ float4 sXY[NCHUNK / 2];   // (x0,x1,y0,y1) of rowB, row-pair packed
    __shared__ float4 sZC[NCHUNK / 2];   // (z0,z1,c0,c1)
    __shared__ float  r1[256], r2[256];
    __shared__ unsigned int s_arr;
    int cta = blockIdx.x;
    int b = cta / (NMT * NCHUNKS);
    int rem = cta % (NMT * NCHUNKS);
    int mtile = rem / NCHUNKS;
    int chunk = rem % NCHUNKS;
    int nbase = chunk * NCHUNK;

    bool liveT = false;
    if (threadIdx.x < NCHUNK / 2) {
        float4 r0 = g_rowB[b][nbase + 2 * threadIdx.x];
        float4 rr = g_rowB[b][nbase + 2 * threadIdx.x + 1];
        sXY[threadIdx.x] = make_float4(r0.x, rr.x, r0.y, rr.y);
        sZC[threadIdx.x] = make_float4(r0.z, rr.z, r0.w, rr.w);
        liveT = (r0.w > -1e29f) || (rr.w > -1e29f);
    }
    int any = __syncthreads_or(liveT ? 1 : 0);
    int m = mtile * MTILE + threadIdx.x;

    if (any) {
        float4 q = g_P2[b][m];
        float qc = lvl2 * q.w;
        ull qxx = pk(q.x, q.x), qyy = pk(q.y, q.y), qzz = pk(q.z, q.z), qcc = pk(qc, qc);
        const __half2* dp = &g_d16[b][nbase >> 1][m];
        ull cs2 = 0ull, csd2 = 0ull;
        #pragma unroll 4
        for (int j = 0; j < NCHUNK / 2; j++) {
            ulonglong2 xy = *reinterpret_cast<const ulonglong2*>(&sXY[j]);   // broadcast
            ulonglong2 zc = *reinterpret_cast<const ulonglong2*>(&sZC[j]);
            ull a = add2(zc.y, qcc);
            a = fma2(xy.x, qxx, a);
            a = fma2(xy.y, qyy, a);
            a = fma2(zc.x, qzz, a);
            float2 af = upk(a);
            ull e = pk(ex2f(af.x), ex2f(af.y));     // includes rowscale (folded as lg2)
            cs2 = add2(cs2, e);
            float2 df = __half22float2(dp[j * kM]);
            csd2 = fma2(e, pk(df.x, df.y), csd2);
        }
        float2 c = upk(cs2), cd = upk(csd2);
        float remR = g_remainR[b][m];
        g_colsum[b][chunk][m]  = (c.x + c.y) * remR;
        g_colsumd[b][chunk][m] = (cd.x + cd.y) * remR;
    } else {
        g_colsum[b][chunk][m]  = 0.0f;
        g_colsumd[b][chunk][m] = 0.0f;
    }

    // -- arrive: elect the last CTA of this (b, mtile) group to run the E phase --
    __threadfence();
    __syncthreads();
    if (threadIdx.x == 0) s_arr = atomicAdd(&g_ticket[b][mtile], 1u);
    __syncthreads();
    if (s_arr != NCHUNKS - 1) return;
    __threadfence();                               // see all groups' partial writes

    float cs = 0.0f, csd = 0.0f;
    #pragma unroll
    for (int c = 0; c < NCHUNKS; c++) { cs += g_colsum[b][c][m]; csd += g_colsumd[b][c][m]; }
    float rr = g_remainR[b][m];
    float csc = fminf(rr / (cs + 1e-9f), 1.0f);
    g_remReff[b][m] = rr * csc;
    float nr = fmaxf(rr - cs * csc, 0.0f);
    g_remainR[b][m] = nr;
    r1[threadIdx.x] = csd * csc;
    r2[threadIdx.x] = nr;
    __syncthreads();
    #pragma unroll
    for (int s = 128; s > 0; s >>= 1) {
        if (threadIdx.x < s) {
            r1[threadIdx.x] += r1[threadIdx.x + s];
            r2[threadIdx.x] += r2[threadIdx.x + s];
        }
        __syncthreads();
    }
    if (threadIdx.x == 0) {
        g_costPart[b][mtile] += r1[0];
        g_sumRPart[b][mtile] = r2[0];
        g_ticket[b][mtile] = 0u;                   // re-arm for next level / next replay
    }
}

// ---------------- final: reduce cost partials into out ----------------
__global__ void k_final(float* __restrict__ out) {
    int b = blockIdx.x;
    int lane = threadIdx.x;
    float v = (lane < NMT) ? g_costPart[b][lane] : 0.0f;
    v = warp_sum(v);
    if (lane == 0) out[b] = v;
}

// ---------------- launch ----------------
extern "C" void kernel_launch(void* const* d_in, const int* in_sizes, int n_in,
                              void* d_out, int out_size) {
    const float* in1 = (const float*)d_in[0];
    const float* in2 = (const float*)d_in[1];
    float* out = (float*)d_out;

    static const float levels[10] = {
        -16384.f, -4096.f, -1024.f, -256.f, -64.f, -16.f, -4.f, -1.f, -0.25f, 0.f
    };

    k_init<<<(kB * kN + 255) / 256, 256>>>(in1, in2);
    k_rowmin<<<kB * (kN / 32), 256>>>();
    k_dprep<<<GRID_B, 256>>>();
    float lp = 0.0f;
    for (int j = 0; j < 10; j++) {
        float lc = levels[j] * LOG2E;
        if (j < 9) k_fusedAC<false><<<GRID_AC, 256>>>(lp, lc);
        else       k_fusedAC<true ><<<GRID_AC, 256>>>(lp, lc);
        k_passBE<<<GRID_B, 256>>>(lc);
        lp = lc;
    }
    k_final<<<kB, 32>>>(out);
}